// round 12
// baseline (speedup 1.0000x reference)
#include <cuda_runtime.h>
#include <cuda_bf16.h>
#include <cuda_fp16.h>
#include <math.h>
#include <stdint.h>

#define LSEQ 2048
#define BSZ 2
#define HID 2560
#define NH 8
#define NKV 4
#define HD 256
#define WIN 512
#define QKVN 4096            // (8+4+4)*256
#define ML (BSZ*LSEQ)        // 4096
#define ODIM (NH*HD)         // 2048

// ---------------- mma.sync helpers (base sm_103 target) ----------------
__device__ __forceinline__ uint32_t s2u(const void* p) {
    uint32_t a;
    asm("{ .reg .u64 t; cvta.to.shared.u64 t, %1; cvt.u32.u64 %0, t; }" : "=r"(a) : "l"(p));
    return a;
}
__device__ __forceinline__ void cp16(uint32_t dst, const void* src) {
    asm volatile("cp.async.cg.shared.global [%0], [%1], 16;" :: "r"(dst), "l"(src));
}
__device__ __forceinline__ void ldsm4(uint32_t* r, uint32_t addr) {
    asm volatile("ldmatrix.sync.aligned.m8n8.x4.shared.b16 {%0,%1,%2,%3}, [%4];"
        : "=r"(r[0]), "=r"(r[1]), "=r"(r[2]), "=r"(r[3]) : "r"(addr));
}
__device__ __forceinline__ void ldsm4t(uint32_t* r, uint32_t addr) {
    asm volatile("ldmatrix.sync.aligned.m8n8.x4.trans.shared.b16 {%0,%1,%2,%3}, [%4];"
        : "=r"(r[0]), "=r"(r[1]), "=r"(r[2]), "=r"(r[3]) : "r"(addr));
}
__device__ __forceinline__ void ldsm2(uint32_t* r, uint32_t addr) {
    asm volatile("ldmatrix.sync.aligned.m8n8.x2.shared.b16 {%0,%1}, [%2];"
        : "=r"(r[0]), "=r"(r[1]) : "r"(addr));
}
__device__ __forceinline__ void mma16816(float* c, const uint32_t* a, const uint32_t* b) {
    asm volatile("mma.sync.aligned.m16n8k16.row.col.f32.bf16.bf16.f32 "
        "{%0,%1,%2,%3}, {%4,%5,%6,%7}, {%8,%9}, {%0,%1,%2,%3};"
        : "+f"(c[0]), "+f"(c[1]), "+f"(c[2]), "+f"(c[3])
        : "r"(a[0]), "r"(a[1]), "r"(a[2]), "r"(a[3]), "r"(b[0]), "r"(b[1]));
}
__device__ __forceinline__ void mma16816h(float* c, const uint32_t* a, const uint32_t* b) {
    asm volatile("mma.sync.aligned.m16n8k16.row.col.f32.f16.f16.f32 "
        "{%0,%1,%2,%3}, {%4,%5,%6,%7}, {%8,%9}, {%0,%1,%2,%3};"
        : "+f"(c[0]), "+f"(c[1]), "+f"(c[2]), "+f"(c[3])
        : "r"(a[0]), "r"(a[1]), "r"(a[2]), "r"(a[3]), "r"(b[0]), "r"(b[1]));
}
#define SW5(x) ((x) ^ (((x) >> 5) & 0x70))   // swizzle for 512B rows

// ---------------- scratch ----------------
__device__ float g_QKV[(size_t)ML * QKVN];
__device__ float g_O[(size_t)ML * ODIM];
__device__ float g_cos[LSEQ * (HD/2)];
__device__ float g_sin[LSEQ * (HD/2)];
// fp16 GEMM operands
__device__ __align__(128) __half g_Xh[(size_t)ML * HID];
__device__ __align__(128) __half g_Wh[(size_t)QKVN * HID];
__device__ __align__(128) __half g_Oh[(size_t)ML * ODIM];
__device__ __align__(128) __half g_OWh[(size_t)HID * ODIM];
// attention operands (bf16 hi/lo)
__device__ __align__(128) __nv_bfloat16 g_Qbh[(size_t)BSZ * NH * LSEQ * HD];
__device__ __align__(128) __nv_bfloat16 g_Qbl[(size_t)BSZ * NH * LSEQ * HD];
__device__ __align__(128) __nv_bfloat16 g_Kbh[(size_t)BSZ * NKV * LSEQ * HD];
__device__ __align__(128) __nv_bfloat16 g_Kbl[(size_t)BSZ * NKV * LSEQ * HD];
__device__ __align__(128) __nv_bfloat16 g_Vbh[(size_t)BSZ * NKV * WIN * HD];
__device__ __align__(128) __nv_bfloat16 g_Vbl[(size_t)BSZ * NKV * WIN * HD];

// ---------------- fp32 -> fp16 convert ----------------
__global__ void cvtf16_kernel(const float* __restrict__ s, __half* __restrict__ h, int n4) {
    int i = blockIdx.x * 256 + threadIdx.x;
    if (i >= n4) return;
    float4 v = ((const float4*)s)[i];
    ((__half2*)h)[2*i]   = __halves2half2(__float2half(v.x), __float2half(v.y));
    ((__half2*)h)[2*i+1] = __halves2half2(__float2half(v.z), __float2half(v.w));
}

// ---------------- fp16 GEMM: C = A @ B^T (fp32 accum/out) ----------------
// Tile 128x256, BK=32, 8 warps (2m x 4n), warp tile 64x64, cp.async double-buffer.
#define BK 32
#define ASTR 80
#define ATILE (128*ASTR)      // 10240
#define BTILE (256*ASTR)      // 20480
#define BUFB  (ATILE+BTILE)   // 30720
#define GEMM_SMEM (2*BUFB)    // 61440

__global__ __launch_bounds__(256)
void gemm_f16(const __half* __restrict__ A, const __half* __restrict__ B,
              float* __restrict__ C, int K, int ldc) {
    extern __shared__ char smg[];
    uint32_t sbase = s2u(smg);
    int t = threadIdx.x, lane = t & 31, wid = t >> 5;
    int warp_m = wid >> 2, warp_n = wid & 3;
    int m0 = blockIdx.x * 128, n0 = blockIdx.y * 256;
    int NC = K / BK;

    float acc[4][8][4];
    #pragma unroll
    for (int mt = 0; mt < 4; mt++)
        #pragma unroll
        for (int nt = 0; nt < 8; nt++)
            #pragma unroll
            for (int q = 0; q < 4; q++) acc[mt][nt][q] = 0.0f;

    int lrow = t >> 2, lkc = t & 3;

#define LOADCHUNK(i, buf) { \
        size_t k0 = (size_t)(i) * BK; \
        uint32_t dbase = sbase + (buf) * BUFB; \
        _Pragma("unroll") \
        for (int j = 0; j < 2; j++) { \
            int row = lrow + j * 64; \
            cp16(dbase + row * ASTR + lkc * 16, \
                 A + (size_t)(m0 + row) * K + k0 + lkc * 8); \
        } \
        _Pragma("unroll") \
        for (int j = 0; j < 4; j++) { \
            int row = lrow + j * 64; \
            cp16(dbase + ATILE + row * ASTR + lkc * 16, \
                 B + (size_t)(n0 + row) * K + k0 + lkc * 8); \
        } \
        asm volatile("cp.async.commit_group;" ::: "memory"); \
    }

    LOADCHUNK(0, 0);

    uint32_t aoffs = (warp_m * 64 + (lane & 15)) * ASTR + (lane >> 4) * 16;
    uint32_t boffs = ATILE + (warp_n * 64 + (lane & 7)) * ASTR + ((lane >> 3) & 1) * 16;

    for (int i = 0; i < NC; i++) {
        int buf = i & 1;
        if (i + 1 < NC) {
            LOADCHUNK(i + 1, buf ^ 1);
            asm volatile("cp.async.wait_group 1;" ::: "memory");
        } else {
            asm volatile("cp.async.wait_group 0;" ::: "memory");
        }
        __syncthreads();

        uint32_t ab = sbase + buf * BUFB + aoffs;
        uint32_t bb = sbase + buf * BUFB + boffs;
        #pragma unroll
        for (int ks = 0; ks < 2; ks++) {
            uint32_t ah[4][4], bh[8][2];
            #pragma unroll
            for (int mt = 0; mt < 4; mt++)
                ldsm4(ah[mt], ab + mt * (16 * ASTR) + ks * 32);
            #pragma unroll
            for (int nt = 0; nt < 8; nt++)
                ldsm2(bh[nt], bb + nt * (8 * ASTR) + ks * 32);
            #pragma unroll
            for (int mt = 0; mt < 4; mt++)
                #pragma unroll
                for (int nt = 0; nt < 8; nt++)
                    mma16816h(acc[mt][nt], ah[mt], bh[nt]);
        }
        __syncthreads();
    }

    #pragma unroll
    for (int mt = 0; mt < 4; mt++) {
        int r = m0 + warp_m * 64 + mt * 16 + (lane >> 2);
        #pragma unroll
        for (int nt = 0; nt < 8; nt++) {
            int cc = n0 + warp_n * 64 + nt * 8 + (lane & 3) * 2;
            *(float2*)(C + (size_t)r * ldc + cc)       = make_float2(acc[mt][nt][0], acc[mt][nt][1]);
            *(float2*)(C + (size_t)(r + 8) * ldc + cc) = make_float2(acc[mt][nt][2], acc[mt][nt][3]);
        }
    }
#undef LOADCHUNK
}

// ---------------- RoPE cos/sin table ----------------
__global__ void rope_table_kernel() {
    int i = threadIdx.x;
    int l = blockIdx.x;
    double inv = exp(-(double)i * (log(10000.0) / 128.0));
    float arg = (float)l * (float)inv;
    g_cos[l * 128 + i] = cosf(arg);
    g_sin[l * 128 + i] = sinf(arg);
}

// ---------------- RMSNorm + RoPE -> bf16 hi/lo ----------------
__global__ void normrope_kernel(const float* __restrict__ qnw, const float* __restrict__ knw) {
    int bl   = blockIdx.x;
    int head = blockIdx.y;
    int d    = threadIdx.x;
    int l = bl & (LSEQ - 1);
    int b = bl >> 11;
    bool isq = head < NH;
    int col = isq ? head * HD + d : NH * HD + (head - NH) * HD + d;

    float x = g_QKV[(size_t)bl * QKVN + col];

    __shared__ float xs[HD];
    __shared__ float red[8];
    float ss = x * x;
    #pragma unroll
    for (int o = 16; o; o >>= 1) ss += __shfl_xor_sync(0xffffffffu, ss, o);
    if ((d & 31) == 0) red[d >> 5] = ss;
    __syncthreads();
    if (d < 8) {
        float v = red[d];
        #pragma unroll
        for (int o = 4; o; o >>= 1) v += __shfl_xor_sync(0xffu, v, o);
        if (d == 0) red[0] = v;
    }
    __syncthreads();
    float rs = rsqrtf(red[0] * (1.0f / HD) + 1e-6f);
    const float* w = isq ? qnw : knw;
    xs[d] = x * rs * (1.0f + w[d]);
    __syncthreads();

    int i = d & 127;
    float cs = g_cos[l * 128 + i];
    float sn = g_sin[l * 128 + i];
    float other = (d < 128) ? -xs[d + 128] : xs[d - 128];
    float out = xs[d] * cs + other * sn;

    __nv_bfloat16 hi = __float2bfloat16(out);
    __nv_bfloat16 lo = __float2bfloat16(out - __bfloat162float(hi));
    if (isq) {
        size_t base = (((size_t)(b * NH + head)) * LSEQ + l) * HD + d;
        g_Qbh[base] = hi; g_Qbl[base] = lo;
    } else {
        size_t base = (((size_t)(b * NKV + head - NH)) * LSEQ + l) * HD + d;
        g_Kbh[base] = hi; g_Kbl[base] = lo;
    }
}

// ---------------- V window split ----------------
__global__ void vsplit_kernel() {
    int bl = blockIdx.x;              // 0..BSZ*WIN-1
    int b  = bl >> 9;
    int li = bl & (WIN - 1);
    int l  = (LSEQ - WIN) + li;
    int d  = threadIdx.x;             // 0..255
    #pragma unroll
    for (int kvh = 0; kvh < NKV; kvh++) {
        float v = g_QKV[((size_t)(b * LSEQ + l)) * QKVN + (NH + NKV) * HD + kvh * HD + d];
        __nv_bfloat16 hi = __float2bfloat16(v);
        __nv_bfloat16 lo = __float2bfloat16(v - __bfloat162float(hi));
        size_t base = (((size_t)(b * NKV + kvh)) * WIN + li) * HD + d;
        g_Vbh[base] = hi; g_Vbl[base] = lo;
    }
}

// ---------------- tensor-core attention (bf16 3-term, unchanged) ----------------
#define AQ 64
#define AK 32
#define NT16 (WIN/AK)         // 16 tiles
#define SQH 0
#define SQL 32768
#define SKH 65536             // + buf*16384
#define SKL 98304
#define SVH 131072
#define SVL 163840
#define SPH 196608
#define SPL 201728
#define SDEN 206848
#define ATTN_SMEM 207104

__global__ __launch_bounds__(256, 1)
void attn_mma(const float* __restrict__ mask) {
    extern __shared__ char sm8[];
    uint32_t sb = s2u(sm8);
    int t = threadIdx.x, lane = t & 31, w = t >> 5;
    int qw = w >> 1, kw = w & 1, dw = w & 1;
    int q0 = blockIdx.x * AQ;
    int h  = blockIdx.y;
    int b  = blockIdx.z;
    int kvh = h >> 1;
    const int S = LSEQ - WIN;

    if (t < AQ) *(float*)(sm8 + SDEN + t * 4) = 0.0f;

    {
        const __nv_bfloat16* Qh = g_Qbh + (((size_t)(b * NH + h)) * LSEQ + q0) * HD;
        const __nv_bfloat16* Ql = g_Qbl + (((size_t)(b * NH + h)) * LSEQ + q0) * HD;
        #pragma unroll
        for (int j = 0; j < 8; j++) {
            int idx = t + 256 * j;
            int row = idx >> 5, ch = idx & 31;
            uint32_t so = SW5(row * 512 + ch * 16);
            cp16(sb + SQH + so, Qh + row * HD + ch * 8);
            cp16(sb + SQL + so, Ql + row * HD + ch * 8);
        }
        asm volatile("cp.async.commit_group;" ::: "memory");
    }

    const __nv_bfloat16* Kh = g_Kbh + (((size_t)(b * NKV + kvh)) * LSEQ + S) * HD;
    const __nv_bfloat16* Kl = g_Kbl + (((size_t)(b * NKV + kvh)) * LSEQ + S) * HD;
    const __nv_bfloat16* Vh = g_Vbh + ((size_t)(b * NKV + kvh)) * WIN * HD;
    const __nv_bfloat16* Vl = g_Vbl + ((size_t)(b * NKV + kvh)) * WIN * HD;

#define TLOAD(i, buf) { \
        size_t koff = (size_t)(i) * AK * HD; \
        _Pragma("unroll") \
        for (int j = 0; j < 4; j++) { \
            int idx = t + 256 * j; \
            int row = idx >> 5, ch = idx & 31; \
            uint32_t so = SW5(row * 512 + ch * 16); \
            size_t g = koff + (size_t)row * HD + ch * 8; \
            cp16(sb + SKH + (buf) * 16384 + so, Kh + g); \
            cp16(sb + SKL + (buf) * 16384 + so, Kl + g); \
            cp16(sb + SVH + (buf) * 16384 + so, Vh + g); \
            cp16(sb + SVL + (buf) * 16384 + so, Vl + g); \
        } \
        asm volatile("cp.async.commit_group;" ::: "memory"); \
    }

    TLOAD(0, 0);

    float o[16][4];
    #pragma unroll
    for (int nt = 0; nt < 16; nt++)
        #pragma unroll
        for (int q = 0; q < 4; q++) o[nt][q] = 0.0f;
    float dreg[2] = {0.0f, 0.0f};

    int ra = qw * 16 + (lane >> 2);

    for (int i = 0; i < NT16; i++) {
        int buf = i & 1;
        if (i + 1 < NT16) {
            TLOAD(i + 1, buf ^ 1);
            asm volatile("cp.async.wait_group 1;" ::: "memory");
        } else {
            asm volatile("cp.async.wait_group 0;" ::: "memory");
        }
        __syncthreads();

        float s[2][4];
        #pragma unroll
        for (int nt = 0; nt < 2; nt++)
            #pragma unroll
            for (int q = 0; q < 4; q++) s[nt][q] = 0.0f;
        {
            int qrow = qw * 16 + (lane & 15);
            int krow = kw * 16 + (lane & 7) + ((lane >> 4) << 3);
            #pragma unroll
            for (int ks = 0; ks < 16; ks++) {
                uint32_t ah[4], al[4], bh[4], bl[4];
                uint32_t qa = sb + SQH + SW5(qrow * 512 + ks * 32 + ((lane >> 4) << 4));
                ldsm4(ah, qa);
                ldsm4(al, qa + (SQL - SQH));
                uint32_t ka = sb + SKH + buf * 16384 +
                              SW5(krow * 512 + ks * 32 + (((lane >> 3) & 1) << 4));
                ldsm4(bh, ka);
                ldsm4(bl, ka + (SKL - SKH));
                mma16816(s[0], ah, bh);
                mma16816(s[0], al, bh);
                mma16816(s[0], ah, bl);
                mma16816(s[1], ah, bh + 2);
                mma16816(s[1], al, bh + 2);
                mma16816(s[1], ah, bl + 2);
            }
        }

        #pragma unroll
        for (int nt = 0; nt < 2; nt++) {
            int kb = kw * 16 + nt * 8 + (lane & 3) * 2;
            int gk = S + i * AK + kb;
            #pragma unroll
            for (int half = 0; half < 2; half++) {
                int row = ra + half * 8;
                float2 mk = *(const float2*)(mask + (size_t)(q0 + row) * LSEQ + gk);
                float v0 = s[nt][half * 2]     * 0.0625f;
                float v1 = s[nt][half * 2 + 1] * 0.0625f;
                float e0 = __expf(v0 * 0.04f);
                float e1 = __expf(v1 * 0.04f);
                float p0 = __expf(mk.x - __fdividef(100.0f, e0 + 1.0f));
                float p1 = __expf(mk.y - __fdividef(100.0f, e1 + 1.0f));
                dreg[half] += p0 + p1;
                __nv_bfloat16 h0 = __float2bfloat16(p0);
                __nv_bfloat16 h1 = __float2bfloat16(p1);
                __nv_bfloat16 l0 = __float2bfloat16(p0 - __bfloat162float(h0));
                __nv_bfloat16 l1 = __float2bfloat16(p1 - __bfloat162float(h1));
                *(__nv_bfloat162*)(sm8 + SPH + row * 80 + kb * 2) = __halves2bfloat162(h0, h1);
                *(__nv_bfloat162*)(sm8 + SPL + row * 80 + kb * 2) = __halves2bfloat162(l0, l1);
            }
        }
        __syncthreads();

        {
            int prow = qw * 16 + (lane & 15);
            int vrowb = (lane & 7) + (((lane >> 3) & 1) << 3);
            #pragma unroll
            for (int ks2 = 0; ks2 < 2; ks2++) {
                uint32_t pah[4], pal[4];
                uint32_t pa = sb + SPH + prow * 80 + ks2 * 32 + ((lane >> 4) << 4);
                ldsm4(pah, pa);
                ldsm4(pal, pa + (SPL - SPH));
                #pragma unroll
                for (int ntp = 0; ntp < 8; ntp++) {
                    uint32_t bvh[4], bvl[4];
                    uint32_t va = sb + SVH + buf * 16384 +
                        SW5((ks2 * 16 + vrowb) * 512 + dw * 256 + ntp * 32 + ((lane >> 4) << 4));
                    ldsm4t(bvh, va);
                    ldsm4t(bvl, va + (SVL - SVH));
                    mma16816(o[2 * ntp],     pah, bvh);
                    mma16816(o[2 * ntp],     pal, bvh);
                    mma16816(o[2 * ntp],     pah, bvl);
                    mma16816(o[2 * ntp + 1], pah, bvh + 2);
                    mma16816(o[2 * ntp + 1], pal, bvh + 2);
                    mma16816(o[2 * ntp + 1], pah, bvl + 2);
                }
            }
        }
        __syncthreads();
    }

    {
        float* denp = (float*)(sm8 + SDEN);
        #pragma unroll
        for (int half = 0; half < 2; half++) {
            float v = dreg[half];
            v += __shfl_xor_sync(0xffffffffu, v, 1);
            v += __shfl_xor_sync(0xffffffffu, v, 2);
            if ((lane & 3) == 0) atomicAdd(denp + ra + half * 8, v);
        }
    }
    __syncthreads();

    {
        float inv0 = 1.0f / *(float*)(sm8 + SDEN + ra * 4);
        float inv1 = 1.0f / *(float*)(sm8 + SDEN + (ra + 8) * 4);
        #pragma unroll
        for (int nt = 0; nt < 16; nt++) {
            int gcol = h * HD + dw * 128 + nt * 8 + (lane & 3) * 2;
            float* O0 = g_O + ((size_t)(b * LSEQ + q0 + ra)) * ODIM + gcol;
            float* O1 = g_O + ((size_t)(b * LSEQ + q0 + ra + 8)) * ODIM + gcol;
            *(float2*)O0 = make_float2(o[nt][0] * inv0, o[nt][1] * inv0);
            *(float2*)O1 = make_float2(o[nt][2] * inv1, o[nt][3] * inv1);
        }
    }
#undef TLOAD
}

// ---------------- launch ----------------
extern "C" void kernel_launch(void* const* d_in, const int* in_sizes, int n_in,
                              void* d_out, int out_size) {
    const float* x    = (const float*)d_in[0];
    const float* mask = (const float*)d_in[1];
    const float* q_w  = (const float*)d_in[2];
    const float* k_w  = (const float*)d_in[3];
    const float* v_w  = (const float*)d_in[4];
    const float* o_w  = (const float*)d_in[5];
    const float* qnw  = (const float*)d_in[6];
    const float* knw  = (const float*)d_in[7];
    float* out = (float*)d_out;

    float *qkv, *obuf;
    __half *xh, *wh, *oh, *owh;
    cudaGetSymbolAddress((void**)&qkv,  g_QKV);
    cudaGetSymbolAddress((void**)&obuf, g_O);
    cudaGetSymbolAddress((void**)&xh,   g_Xh);
    cudaGetSymbolAddress((void**)&wh,   g_Wh);
    cudaGetSymbolAddress((void**)&oh,   g_Oh);
    cudaGetSymbolAddress((void**)&owh,  g_OWh);

    cudaFuncSetAttribute(gemm_f16, cudaFuncAttributeMaxDynamicSharedMemorySize, GEMM_SMEM);
    cudaFuncSetAttribute(attn_mma, cudaFuncAttributeMaxDynamicSharedMemorySize, ATTN_SMEM);

    // fp16 operand prep first (launches 1-5) so gemm_f16 is launch #6 -> ncu captures it
    {
        int n4 = (ML * HID) / 4;
        cvtf16_kernel<<<(n4 + 255) / 256, 256>>>(x, xh, n4);
        n4 = (NH * HD * HID) / 4;
        cvtf16_kernel<<<(n4 + 255) / 256, 256>>>(q_w, wh, n4);
        n4 = (NKV * HD * HID) / 4;
        cvtf16_kernel<<<(n4 + 255) / 256, 256>>>(k_w, wh + (size_t)NH*HD*HID, n4);
        cvtf16_kernel<<<(n4 + 255) / 256, 256>>>(v_w, wh + (size_t)(NH+NKV)*HD*HID, n4);
        n4 = (HID * ODIM) / 4;
        cvtf16_kernel<<<(n4 + 255) / 256, 256>>>(o_w, owh, n4);
    }

    // QKV projection: g_QKV[4096, 4096] = X @ W^T, K=2560   (launch #6)
    gemm_f16<<<dim3(ML / 128, QKVN / 256), 256, GEMM_SMEM>>>(xh, wh, qkv, HID, QKVN);

    rope_table_kernel<<<LSEQ, 128>>>();
    normrope_kernel<<<dim3(ML, NH + NKV), 256>>>(qnw, knw);
    vsplit_kernel<<<BSZ * WIN, 256>>>();

    attn_mma<<<dim3(LSEQ / AQ, NH, BSZ), 256, ATTN_SMEM>>>(mask);

    // O projection: out = O @ o_w^T, K=2048
    {
        int n4 = (ML * ODIM) / 4;
        cvtf16_kernel<<<(n4 + 255) / 256, 256>>>(obuf, oh, n4);
    }
    gemm_f16<<<dim3(ML / 128, HID / 256), 256, GEMM_SMEM>>>(oh, owh, out, ODIM, HID);
}

// round 13
// speedup vs baseline: 1.1402x; 1.1402x over previous
#include <cuda_runtime.h>
#include <cuda_bf16.h>
#include <cuda_fp16.h>
#include <math.h>
#include <stdint.h>

#define LSEQ 2048
#define BSZ 2
#define HID 2560
#define NH 8
#define NKV 4
#define HD 256
#define WIN 512
#define QKVN 4096            // (8+4+4)*256
#define ML (BSZ*LSEQ)        // 4096
#define ODIM (NH*HD)         // 2048

// ---------------- mma.sync helpers (base sm_103 target) ----------------
__device__ __forceinline__ uint32_t s2u(const void* p) {
    uint32_t a;
    asm("{ .reg .u64 t; cvta.to.shared.u64 t, %1; cvt.u32.u64 %0, t; }" : "=r"(a) : "l"(p));
    return a;
}
__device__ __forceinline__ void cp16(uint32_t dst, const void* src) {
    asm volatile("cp.async.cg.shared.global [%0], [%1], 16;" :: "r"(dst), "l"(src));
}
__device__ __forceinline__ void ldsm4(uint32_t* r, uint32_t addr) {
    asm volatile("ldmatrix.sync.aligned.m8n8.x4.shared.b16 {%0,%1,%2,%3}, [%4];"
        : "=r"(r[0]), "=r"(r[1]), "=r"(r[2]), "=r"(r[3]) : "r"(addr));
}
__device__ __forceinline__ void ldsm4t(uint32_t* r, uint32_t addr) {
    asm volatile("ldmatrix.sync.aligned.m8n8.x4.trans.shared.b16 {%0,%1,%2,%3}, [%4];"
        : "=r"(r[0]), "=r"(r[1]), "=r"(r[2]), "=r"(r[3]) : "r"(addr));
}
__device__ __forceinline__ void ldsm2(uint32_t* r, uint32_t addr) {
    asm volatile("ldmatrix.sync.aligned.m8n8.x2.shared.b16 {%0,%1}, [%2];"
        : "=r"(r[0]), "=r"(r[1]) : "r"(addr));
}
__device__ __forceinline__ void mma16816(float* c, const uint32_t* a, const uint32_t* b) {
    asm volatile("mma.sync.aligned.m16n8k16.row.col.f32.bf16.bf16.f32 "
        "{%0,%1,%2,%3}, {%4,%5,%6,%7}, {%8,%9}, {%0,%1,%2,%3};"
        : "+f"(c[0]), "+f"(c[1]), "+f"(c[2]), "+f"(c[3])
        : "r"(a[0]), "r"(a[1]), "r"(a[2]), "r"(a[3]), "r"(b[0]), "r"(b[1]));
}
__device__ __forceinline__ void mma16816h(float* c, const uint32_t* a, const uint32_t* b) {
    asm volatile("mma.sync.aligned.m16n8k16.row.col.f32.f16.f16.f32 "
        "{%0,%1,%2,%3}, {%4,%5,%6,%7}, {%8,%9}, {%0,%1,%2,%3};"
        : "+f"(c[0]), "+f"(c[1]), "+f"(c[2]), "+f"(c[3])
        : "r"(a[0]), "r"(a[1]), "r"(a[2]), "r"(a[3]), "r"(b[0]), "r"(b[1]));
}
#define SW5(x) ((x) ^ (((x) >> 5) & 0x70))   // swizzle for 512B rows

// ---------------- scratch ----------------
__device__ float g_QKV[(size_t)ML * QKVN];
__device__ float g_cos[LSEQ * (HD/2)];
__device__ float g_sin[LSEQ * (HD/2)];
// fp16 GEMM operands
__device__ __align__(128) __half g_Xh[(size_t)ML * HID];
__device__ __align__(128) __half g_Wh[(size_t)QKVN * HID];
__device__ __align__(128) __half g_Oh[(size_t)ML * ODIM];   // attention out (fp16, direct)
__device__ __align__(128) __half g_OWh[(size_t)HID * ODIM];
// attention operands (bf16 hi/lo)
__device__ __align__(128) __nv_bfloat16 g_Qbh[(size_t)BSZ * NH * LSEQ * HD];
__device__ __align__(128) __nv_bfloat16 g_Qbl[(size_t)BSZ * NH * LSEQ * HD];
__device__ __align__(128) __nv_bfloat16 g_Kbh[(size_t)BSZ * NKV * LSEQ * HD];
__device__ __align__(128) __nv_bfloat16 g_Kbl[(size_t)BSZ * NKV * LSEQ * HD];
__device__ __align__(128) __nv_bfloat16 g_Vbh[(size_t)BSZ * NKV * WIN * HD];
__device__ __align__(128) __nv_bfloat16 g_Vbl[(size_t)BSZ * NKV * WIN * HD];

// ---------------- fp32 -> fp16 convert ----------------
__global__ void cvtf16_kernel(const float* __restrict__ s, __half* __restrict__ h, int n4) {
    int i = blockIdx.x * 256 + threadIdx.x;
    if (i >= n4) return;
    float4 v = ((const float4*)s)[i];
    ((__half2*)h)[2*i]   = __halves2half2(__float2half(v.x), __float2half(v.y));
    ((__half2*)h)[2*i+1] = __halves2half2(__float2half(v.z), __float2half(v.w));
}

// ---------------- fp16 GEMM: C = A @ B^T (fp32 accum/out), round-11 config ----------------
// Tile 128x128, BK=32, 8 warps (2m x 4n), cp.async double-buffer, 1 MMA chain.
#define BK 32
#define ASTR 80
#define TILEB 10240
#define BUFB  20480          // 2 tiles (A, B)
#define GEMM_SMEM (2*BUFB)

__global__ __launch_bounds__(256)
void gemm_f16(const __half* __restrict__ A, const __half* __restrict__ B,
              float* __restrict__ C, int K, int ldc) {
    extern __shared__ char smg[];
    uint32_t sbase = s2u(smg);
    int t = threadIdx.x, lane = t & 31, wid = t >> 5;
    int warp_m = wid >> 2, warp_n = wid & 3;
    int m0 = blockIdx.x * 128, n0 = blockIdx.y * 128;
    int NC = K / BK;

    float acc[4][4][4];
    #pragma unroll
    for (int mt = 0; mt < 4; mt++)
        #pragma unroll
        for (int nt = 0; nt < 4; nt++)
            #pragma unroll
            for (int q = 0; q < 4; q++) acc[mt][nt][q] = 0.0f;

    int lrow = t >> 2, lkc = t & 3;

#define LOADCHUNK(i, buf) { \
        size_t k0 = (size_t)(i) * BK; \
        uint32_t dbase = sbase + (buf) * BUFB; \
        _Pragma("unroll") \
        for (int j = 0; j < 2; j++) { \
            int row = lrow + j * 64; \
            uint32_t dst = dbase + row * ASTR + lkc * 16; \
            size_t ga = (size_t)(m0 + row) * K + k0 + lkc * 8; \
            size_t gb = (size_t)(n0 + row) * K + k0 + lkc * 8; \
            cp16(dst,         A + ga); \
            cp16(dst + TILEB, B + gb); \
        } \
        asm volatile("cp.async.commit_group;" ::: "memory"); \
    }

    LOADCHUNK(0, 0);

    uint32_t aoffs = (warp_m * 64 + (lane & 15)) * ASTR + (lane >> 4) * 16;
    uint32_t boffs = TILEB + (warp_n * 32 + (lane & 7)) * ASTR + ((lane >> 3) & 1) * 16;

    for (int i = 0; i < NC; i++) {
        int buf = i & 1;
        if (i + 1 < NC) {
            LOADCHUNK(i + 1, buf ^ 1);
            asm volatile("cp.async.wait_group 1;" ::: "memory");
        } else {
            asm volatile("cp.async.wait_group 0;" ::: "memory");
        }
        __syncthreads();

        uint32_t ab = sbase + buf * BUFB + aoffs;
        uint32_t bb = sbase + buf * BUFB + boffs;
        #pragma unroll
        for (int ks = 0; ks < 2; ks++) {
            uint32_t ah[4][4], bh[4][2];
            #pragma unroll
            for (int mt = 0; mt < 4; mt++)
                ldsm4(ah[mt], ab + mt * (16 * ASTR) + ks * 32);
            #pragma unroll
            for (int nt = 0; nt < 4; nt++)
                ldsm2(bh[nt], bb + nt * (8 * ASTR) + ks * 32);
            #pragma unroll
            for (int mt = 0; mt < 4; mt++)
                #pragma unroll
                for (int nt = 0; nt < 4; nt++)
                    mma16816h(acc[mt][nt], ah[mt], bh[nt]);
        }
        __syncthreads();
    }

    #pragma unroll
    for (int mt = 0; mt < 4; mt++) {
        int r = m0 + warp_m * 64 + mt * 16 + (lane >> 2);
        #pragma unroll
        for (int nt = 0; nt < 4; nt++) {
            int cc = n0 + warp_n * 32 + nt * 8 + (lane & 3) * 2;
            *(float2*)(C + (size_t)r * ldc + cc)       = make_float2(acc[mt][nt][0], acc[mt][nt][1]);
            *(float2*)(C + (size_t)(r + 8) * ldc + cc) = make_float2(acc[mt][nt][2], acc[mt][nt][3]);
        }
    }
#undef LOADCHUNK
}

// ---------------- RoPE cos/sin table ----------------
__global__ void rope_table_kernel() {
    int i = threadIdx.x;
    int l = blockIdx.x;
    double inv = exp(-(double)i * (log(10000.0) / 128.0));
    float arg = (float)l * (float)inv;
    g_cos[l * 128 + i] = cosf(arg);
    g_sin[l * 128 + i] = sinf(arg);
}

// ---------------- RMSNorm + RoPE -> bf16 hi/lo ----------------
__global__ void normrope_kernel(const float* __restrict__ qnw, const float* __restrict__ knw) {
    int bl   = blockIdx.x;
    int head = blockIdx.y;
    int d    = threadIdx.x;
    int l = bl & (LSEQ - 1);
    int b = bl >> 11;
    bool isq = head < NH;
    int col = isq ? head * HD + d : NH * HD + (head - NH) * HD + d;

    float x = g_QKV[(size_t)bl * QKVN + col];

    __shared__ float xs[HD];
    __shared__ float red[8];
    float ss = x * x;
    #pragma unroll
    for (int o = 16; o; o >>= 1) ss += __shfl_xor_sync(0xffffffffu, ss, o);
    if ((d & 31) == 0) red[d >> 5] = ss;
    __syncthreads();
    if (d < 8) {
        float v = red[d];
        #pragma unroll
        for (int o = 4; o; o >>= 1) v += __shfl_xor_sync(0xffu, v, o);
        if (d == 0) red[0] = v;
    }
    __syncthreads();
    float rs = rsqrtf(red[0] * (1.0f / HD) + 1e-6f);
    const float* w = isq ? qnw : knw;
    xs[d] = x * rs * (1.0f + w[d]);
    __syncthreads();

    int i = d & 127;
    float cs = g_cos[l * 128 + i];
    float sn = g_sin[l * 128 + i];
    float other = (d < 128) ? -xs[d + 128] : xs[d - 128];
    float out = xs[d] * cs + other * sn;

    __nv_bfloat16 hi = __float2bfloat16(out);
    __nv_bfloat16 lo = __float2bfloat16(out - __bfloat162float(hi));
    if (isq) {
        size_t base = (((size_t)(b * NH + head)) * LSEQ + l) * HD + d;
        g_Qbh[base] = hi; g_Qbl[base] = lo;
    } else {
        size_t base = (((size_t)(b * NKV + head - NH)) * LSEQ + l) * HD + d;
        g_Kbh[base] = hi; g_Kbl[base] = lo;
    }
}

// ---------------- V window split ----------------
__global__ void vsplit_kernel() {
    int bl = blockIdx.x;              // 0..BSZ*WIN-1
    int b  = bl >> 9;
    int li = bl & (WIN - 1);
    int l  = (LSEQ - WIN) + li;
    int d  = threadIdx.x;             // 0..255
    #pragma unroll
    for (int kvh = 0; kvh < NKV; kvh++) {
        float v = g_QKV[((size_t)(b * LSEQ + l)) * QKVN + (NH + NKV) * HD + kvh * HD + d];
        __nv_bfloat16 hi = __float2bfloat16(v);
        __nv_bfloat16 lo = __float2bfloat16(v - __bfloat162float(hi));
        size_t base = (((size_t)(b * NKV + kvh)) * WIN + li) * HD + d;
        g_Vbh[base] = hi; g_Vbl[base] = lo;
    }
}

// ---------------- tensor-core attention (bf16 3-term), fp16 direct output ----------------
#define AQ 64
#define AK 32
#define NT16 (WIN/AK)         // 16 tiles
#define SQH 0
#define SQL 32768
#define SKH 65536             // + buf*16384
#define SKL 98304
#define SVH 131072
#define SVL 163840
#define SPH 196608
#define SPL 201728
#define SDEN 206848
#define ATTN_SMEM 207104

__global__ __launch_bounds__(256, 1)
void attn_mma(const float* __restrict__ mask) {
    extern __shared__ char sm8[];
    uint32_t sb = s2u(sm8);
    int t = threadIdx.x, lane = t & 31, w = t >> 5;
    int qw = w >> 1, kw = w & 1, dw = w & 1;
    int q0 = blockIdx.x * AQ;
    int h  = blockIdx.y;
    int b  = blockIdx.z;
    int kvh = h >> 1;
    const int S = LSEQ - WIN;

    if (t < AQ) *(float*)(sm8 + SDEN + t * 4) = 0.0f;

    {
        const __nv_bfloat16* Qh = g_Qbh + (((size_t)(b * NH + h)) * LSEQ + q0) * HD;
        const __nv_bfloat16* Ql = g_Qbl + (((size_t)(b * NH + h)) * LSEQ + q0) * HD;
        #pragma unroll
        for (int j = 0; j < 8; j++) {
            int idx = t + 256 * j;
            int row = idx >> 5, ch = idx & 31;
            uint32_t so = SW5(row * 512 + ch * 16);
            cp16(sb + SQH + so, Qh + row * HD + ch * 8);
            cp16(sb + SQL + so, Ql + row * HD + ch * 8);
        }
        asm volatile("cp.async.commit_group;" ::: "memory");
    }

    const __nv_bfloat16* Kh = g_Kbh + (((size_t)(b * NKV + kvh)) * LSEQ + S) * HD;
    const __nv_bfloat16* Kl = g_Kbl + (((size_t)(b * NKV + kvh)) * LSEQ + S) * HD;
    const __nv_bfloat16* Vh = g_Vbh + ((size_t)(b * NKV + kvh)) * WIN * HD;
    const __nv_bfloat16* Vl = g_Vbl + ((size_t)(b * NKV + kvh)) * WIN * HD;

#define TLOAD(i, buf) { \
        size_t koff = (size_t)(i) * AK * HD; \
        _Pragma("unroll") \
        for (int j = 0; j < 4; j++) { \
            int idx = t + 256 * j; \
            int row = idx >> 5, ch = idx & 31; \
            uint32_t so = SW5(row * 512 + ch * 16); \
            size_t g = koff + (size_t)row * HD + ch * 8; \
            cp16(sb + SKH + (buf) * 16384 + so, Kh + g); \
            cp16(sb + SKL + (buf) * 16384 + so, Kl + g); \
            cp16(sb + SVH + (buf) * 16384 + so, Vh + g); \
            cp16(sb + SVL + (buf) * 16384 + so, Vl + g); \
        } \
        asm volatile("cp.async.commit_group;" ::: "memory"); \
    }

    TLOAD(0, 0);

    float o[16][4];
    #pragma unroll
    for (int nt = 0; nt < 16; nt++)
        #pragma unroll
        for (int q = 0; q < 4; q++) o[nt][q] = 0.0f;
    float dreg[2] = {0.0f, 0.0f};

    int ra = qw * 16 + (lane >> 2);

    for (int i = 0; i < NT16; i++) {
        int buf = i & 1;
        if (i + 1 < NT16) {
            TLOAD(i + 1, buf ^ 1);
            asm volatile("cp.async.wait_group 1;" ::: "memory");
        } else {
            asm volatile("cp.async.wait_group 0;" ::: "memory");
        }
        __syncthreads();

        float s[2][4];
        #pragma unroll
        for (int nt = 0; nt < 2; nt++)
            #pragma unroll
            for (int q = 0; q < 4; q++) s[nt][q] = 0.0f;
        {
            int qrow = qw * 16 + (lane & 15);
            int krow = kw * 16 + (lane & 7) + ((lane >> 4) << 3);
            #pragma unroll
            for (int ks = 0; ks < 16; ks++) {
                uint32_t ah[4], al[4], bh[4], bl[4];
                uint32_t qa = sb + SQH + SW5(qrow * 512 + ks * 32 + ((lane >> 4) << 4));
                ldsm4(ah, qa);
                ldsm4(al, qa + (SQL - SQH));
                uint32_t ka = sb + SKH + buf * 16384 +
                              SW5(krow * 512 + ks * 32 + (((lane >> 3) & 1) << 4));
                ldsm4(bh, ka);
                ldsm4(bl, ka + (SKL - SKH));
                mma16816(s[0], ah, bh);
                mma16816(s[0], al, bh);
                mma16816(s[0], ah, bl);
                mma16816(s[1], ah, bh + 2);
                mma16816(s[1], al, bh + 2);
                mma16816(s[1], ah, bl + 2);
            }
        }

        #pragma unroll
        for (int nt = 0; nt < 2; nt++) {
            int kb = kw * 16 + nt * 8 + (lane & 3) * 2;
            int gk = S + i * AK + kb;
            #pragma unroll
            for (int half = 0; half < 2; half++) {
                int row = ra + half * 8;
                float2 mk = *(const float2*)(mask + (size_t)(q0 + row) * LSEQ + gk);
                float v0 = s[nt][half * 2]     * 0.0625f;
                float v1 = s[nt][half * 2 + 1] * 0.0625f;
                float e0 = __expf(v0 * 0.04f);
                float e1 = __expf(v1 * 0.04f);
                float p0 = __expf(mk.x - __fdividef(100.0f, e0 + 1.0f));
                float p1 = __expf(mk.y - __fdividef(100.0f, e1 + 1.0f));
                dreg[half] += p0 + p1;
                __nv_bfloat16 h0 = __float2bfloat16(p0);
                __nv_bfloat16 h1 = __float2bfloat16(p1);
                __nv_bfloat16 l0 = __float2bfloat16(p0 - __bfloat162float(h0));
                __nv_bfloat16 l1 = __float2bfloat16(p1 - __bfloat162float(h1));
                *(__nv_bfloat162*)(sm8 + SPH + row * 80 + kb * 2) = __halves2bfloat162(h0, h1);
                *(__nv_bfloat162*)(sm8 + SPL + row * 80 + kb * 2) = __halves2bfloat162(l0, l1);
            }
        }
        __syncthreads();

        {
            int prow = qw * 16 + (lane & 15);
            int vrowb = (lane & 7) + (((lane >> 3) & 1) << 3);
            #pragma unroll
            for (int ks2 = 0; ks2 < 2; ks2++) {
                uint32_t pah[4], pal[4];
                uint32_t pa = sb + SPH + prow * 80 + ks2 * 32 + ((lane >> 4) << 4);
                ldsm4(pah, pa);
                ldsm4(pal, pa + (SPL - SPH));
                #pragma unroll
                for (int ntp = 0; ntp < 8; ntp++) {
                    uint32_t bvh[4], bvl[4];
                    uint32_t va = sb + SVH + buf * 16384 +
                        SW5((ks2 * 16 + vrowb) * 512 + dw * 256 + ntp * 32 + ((lane >> 4) << 4));
                    ldsm4t(bvh, va);
                    ldsm4t(bvl, va + (SVL - SVH));
                    mma16816(o[2 * ntp],     pah, bvh);
                    mma16816(o[2 * ntp],     pal, bvh);
                    mma16816(o[2 * ntp],     pah, bvl);
                    mma16816(o[2 * ntp + 1], pah, bvh + 2);
                    mma16816(o[2 * ntp + 1], pal, bvh + 2);
                    mma16816(o[2 * ntp + 1], pah, bvl + 2);
                }
            }
        }
        __syncthreads();
    }

    {
        float* denp = (float*)(sm8 + SDEN);
        #pragma unroll
        for (int half = 0; half < 2; half++) {
            float v = dreg[half];
            v += __shfl_xor_sync(0xffffffffu, v, 1);
            v += __shfl_xor_sync(0xffffffffu, v, 2);
            if ((lane & 3) == 0) atomicAdd(denp + ra + half * 8, v);
        }
    }
    __syncthreads();

    // fp16 direct output (fuses the former cvtf16(obuf) pass)
    {
        float inv0 = 1.0f / *(float*)(sm8 + SDEN + ra * 4);
        float inv1 = 1.0f / *(float*)(sm8 + SDEN + (ra + 8) * 4);
        #pragma unroll
        for (int nt = 0; nt < 16; nt++) {
            int gcol = h * HD + dw * 128 + nt * 8 + (lane & 3) * 2;
            __half* O0 = g_Oh + ((size_t)(b * LSEQ + q0 + ra)) * ODIM + gcol;
            __half* O1 = g_Oh + ((size_t)(b * LSEQ + q0 + ra + 8)) * ODIM + gcol;
            *(__half2*)O0 = __halves2half2(__float2half(o[nt][0] * inv0),
                                           __float2half(o[nt][1] * inv0));
            *(__half2*)O1 = __halves2half2(__float2half(o[nt][2] * inv1),
                                           __float2half(o[nt][3] * inv1));
        }
    }
#undef TLOAD
}

// ---------------- launch ----------------
extern "C" void kernel_launch(void* const* d_in, const int* in_sizes, int n_in,
                              void* d_out, int out_size) {
    const float* x    = (const float*)d_in[0];
    const float* mask = (const float*)d_in[1];
    const float* q_w  = (const float*)d_in[2];
    const float* k_w  = (const float*)d_in[3];
    const float* v_w  = (const float*)d_in[4];
    const float* o_w  = (const float*)d_in[5];
    const float* qnw  = (const float*)d_in[6];
    const float* knw  = (const float*)d_in[7];
    float* out = (float*)d_out;

    float* qkv;
    __half *xh, *wh, *oh, *owh;
    cudaGetSymbolAddress((void**)&qkv, g_QKV);
    cudaGetSymbolAddress((void**)&xh,  g_Xh);
    cudaGetSymbolAddress((void**)&wh,  g_Wh);
    cudaGetSymbolAddress((void**)&oh,  g_Oh);
    cudaGetSymbolAddress((void**)&owh, g_OWh);

    cudaFuncSetAttribute(gemm_f16, cudaFuncAttributeMaxDynamicSharedMemorySize, GEMM_SMEM);
    cudaFuncSetAttribute(attn_mma, cudaFuncAttributeMaxDynamicSharedMemorySize, ATTN_SMEM);

    rope_table_kernel<<<LSEQ, 128>>>();

    // fp16 operand prep
    {
        int n4 = (ML * HID) / 4;
        cvtf16_kernel<<<(n4 + 255) / 256, 256>>>(x, xh, n4);
        n4 = (NH * HD * HID) / 4;
        cvtf16_kernel<<<(n4 + 255) / 256, 256>>>(q_w, wh, n4);
        n4 = (NKV * HD * HID) / 4;
        cvtf16_kernel<<<(n4 + 255) / 256, 256>>>(k_w, wh + (size_t)NH*HD*HID, n4);
        cvtf16_kernel<<<(n4 + 255) / 256, 256>>>(v_w, wh + (size_t)(NH+NKV)*HD*HID, n4);
        n4 = (HID * ODIM) / 4;
        cvtf16_kernel<<<(n4 + 255) / 256, 256>>>(o_w, owh, n4);
    }

    // QKV projection: g_QKV[4096, 4096] = X @ W^T, K=2560
    gemm_f16<<<dim3(ML / 128, QKVN / 128), 256, GEMM_SMEM>>>(xh, wh, qkv, HID, QKVN);

    normrope_kernel<<<dim3(ML, NH + NKV), 256>>>(qnw, knw);
    vsplit_kernel<<<BSZ * WIN, 256>>>();

    attn_mma<<<dim3(LSEQ / AQ, NH, BSZ), 256, ATTN_SMEM>>>(mask);

    // O projection: out = O @ o_w^T, K=2048  (attn wrote g_Oh fp16 directly)
    gemm_f16<<<dim3(ML / 128, HID / 128), 256, GEMM_SMEM>>>(oh, owh, out, ODIM, HID);
}